// round 2
// baseline (speedup 1.0000x reference)
#include <cuda_runtime.h>
#include <math.h>

// Problem constants
#define IC   32          // in capsules
#define DDIM 288         // ich*w*h
#define OC   10          // out capsules
#define CH   16          // out channels
#define BSZ  64          // batch
#define JDIM 160         // OC*CH
#define NT   10240       // BSZ*OC*CH
#define RBLK 32          // routing blocks (== warp size for easy reductions)
#define RTPB 320         // routing threads per block (RBLK*RTPB == NT)

// Scratch (device globals: no allocation allowed)
__device__ float g_usum[IC * NT];                 // [i][o][b][c]
__device__ float g_udot[IC * OC];                 // [i][o]
__device__ __align__(128) float g_part[3][RBLK];  // per-iter L1 partials (one L1 line each)
__device__ unsigned g_bar_cnt = 0;
__device__ unsigned g_bar_gen = 0;

// ---------------------------------------------------------------------------
// K1: u_sum[b,i,o,c] = sum_d u[b,i,d] * W[i,d,o,c]
// grid = 32 i * 5 j-chunks(32 wide) = 160 blocks, 256 threads.
// Packed f32x2 FMA: accumulators pack a batch PAIR (2ty, 2ty+1); u pairs come
// packed from a transposed smem tile; W stored duplicated (w,w) in smem.
// Per thread: 4 packed accumulators = 8 outputs (2 b x 4 j).
// ---------------------------------------------------------------------------
__global__ __launch_bounds__(256) void k1_gemm(const float* __restrict__ u,
                                               const float* __restrict__ W) {
    const int i  = blockIdx.x / 5;
    const int jc = blockIdx.x % 5;
    const int j0 = jc * 32;
    const int tid = threadIdx.x;
    const int tx = tid & 7;    // j group of 4: j = j0 + tx*4 + jj
    const int ty = tid >> 3;   // 0..31: batch pair (2ty, 2ty+1)

    __shared__ float  u_t[48][66];     // transposed u chunk [dd][b], pad 66 (8B-aligned pairs, 2-way STS)
    __shared__ float2 w_s2[48][32];    // duplicated W chunk [dd][j] = (w,w)
    __shared__ float  red[256];

    unsigned long long acc0 = 0ull, acc1 = 0ull, acc2 = 0ull, acc3 = 0ull;

    const float* ug = u + i * DDIM;
    const float* wg = W + (size_t)i * DDIM * JDIM + j0;

    float upf[12];   // 48*64/256
    float wpf[6];    // 48*32/256

    // prefetch chunk 0
    {
#pragma unroll
        for (int p = 0; p < 12; p++) {
            int e = tid + p * 256;
            int b = e / 48, dd = e - b * 48;
            upf[p] = ug[b * (IC * DDIM) + dd];
        }
#pragma unroll
        for (int p = 0; p < 6; p++) {
            int e = tid + p * 256;
            int dd = e >> 5, j = e & 31;
            wpf[p] = wg[dd * JDIM + j];
        }
    }

    for (int c = 0; c < 6; c++) {
        __syncthreads();   // smem free from previous compute
#pragma unroll
        for (int p = 0; p < 12; p++) {
            int e = tid + p * 256;
            int b = e / 48, dd = e - b * 48;
            u_t[dd][b] = upf[p];
        }
#pragma unroll
        for (int p = 0; p < 6; p++) {
            int e = tid + p * 256;
            int dd = e >> 5, j = e & 31;
            w_s2[dd][j] = make_float2(wpf[p], wpf[p]);
        }
        __syncthreads();
        if (c < 5) {
            const int d0 = (c + 1) * 48;
#pragma unroll
            for (int p = 0; p < 12; p++) {
                int e = tid + p * 256;
                int b = e / 48, dd = e - b * 48;
                upf[p] = ug[b * (IC * DDIM) + d0 + dd];
            }
#pragma unroll
            for (int p = 0; p < 6; p++) {
                int e = tid + p * 256;
                int dd = e >> 5, j = e & 31;
                wpf[p] = wg[(d0 + dd) * JDIM + j];
            }
        }
#pragma unroll 16
        for (int dd = 0; dd < 48; dd++) {
            unsigned long long ub = *(const unsigned long long*)&u_t[dd][ty * 2];
            ulonglong2 wa = *(const ulonglong2*)&w_s2[dd][tx * 4];
            ulonglong2 wb = *(const ulonglong2*)&w_s2[dd][tx * 4 + 2];
            asm("fma.rn.f32x2 %0, %1, %2, %0;" : "+l"(acc0) : "l"(ub), "l"(wa.x));
            asm("fma.rn.f32x2 %0, %1, %2, %0;" : "+l"(acc1) : "l"(ub), "l"(wa.y));
            asm("fma.rn.f32x2 %0, %1, %2, %0;" : "+l"(acc2) : "l"(ub), "l"(wb.x));
            asm("fma.rn.f32x2 %0, %1, %2, %0;" : "+l"(acc3) : "l"(ub), "l"(wb.y));
        }
    }

    // unpack + store u_sum + per-thread sum for u_dot
    unsigned long long accs[4] = {acc0, acc1, acc2, acc3};
    float lsum = 0.f;
#pragma unroll
    for (int jj = 0; jj < 4; jj++) {
        float v0 = __uint_as_float((unsigned)(accs[jj] & 0xffffffffull));
        float v1 = __uint_as_float((unsigned)(accs[jj] >> 32));
        int j = j0 + tx * 4 + jj;
        int o = j >> 4, ch = j & 15;
        g_usum[((i * OC + o) * BSZ + 2 * ty) * CH + ch]     = v0;
        g_usum[((i * OC + o) * BSZ + 2 * ty + 1) * CH + ch] = v1;
        lsum += v0 + v1;
    }
    red[tid] = lsum;
    __syncthreads();
    // this thread's 8 outputs all share one o: o = 2jc + (tx>=4).
    // deterministic serial reduction by two threads.
    if (tid < 2) {
        float s = 0.f;
        for (int k = 0; k < 256; k++) {
            if ((((k & 7) >= 4) ? 1 : 0) == tid) s += red[k];
        }
        g_udot[i * OC + 2 * jc + tid] = s;
    }
}

// ---------------------------------------------------------------------------
// warp reductions (butterfly: deterministic)
// ---------------------------------------------------------------------------
__device__ __forceinline__ float warp_sum_f(float v) {
#pragma unroll
    for (int o = 16; o > 0; o >>= 1) v += __shfl_xor_sync(0xffffffffu, v, o);
    return v;
}
__device__ __forceinline__ float warp_max_f(float v) {
#pragma unroll
    for (int o = 16; o > 0; o >>= 1) v = fmaxf(v, __shfl_xor_sync(0xffffffffu, v, o));
    return v;
}

// ---------------------------------------------------------------------------
// software grid barrier (sense-reversal via generation counter).
// All RBLK blocks are guaranteed co-resident (RBLK=32 << 148 SMs).
// Returns counter to 0 each time -> safe across graph replays.
// ---------------------------------------------------------------------------
__device__ __forceinline__ void grid_barrier() {
    __syncthreads();
    if (threadIdx.x == 0) {
        __threadfence();
        unsigned gen = atomicAdd(&g_bar_gen, 0u);     // snapshot before arriving
        unsigned a = atomicAdd(&g_bar_cnt, 1u);
        if (a == RBLK - 1) {
            atomicExch(&g_bar_cnt, 0u);
            __threadfence();
            atomicAdd(&g_bar_gen, 1u);
        } else {
            while (atomicAdd(&g_bar_gen, 0u) == gen) __nanosleep(32);
        }
        __threadfence();
    }
    __syncthreads();
}

// block L1-partial: warp reduce then serial 10-sum by thread 0 (deterministic)
__device__ __forceinline__ void block_part(float v, float* redw, int it) {
    float ws = warp_sum_f(fabsf(v));
    if ((threadIdx.x & 31) == 0) redw[threadIdx.x >> 5] = ws;
    __syncthreads();
    if (threadIdx.x == 0) {
        float a = 0.f;
#pragma unroll
        for (int k = 0; k < RTPB / 32; k++) a += redw[k];
        g_part[it][blockIdx.x] = a;
    }
}

// coupling: warp w (< OC) handles output capsule o=w; lane = input capsule i.
// b_t[i,o] = u_dot[i,o] * g_t[o] (rank-1 recurrence); returns c_t via softmax.
__device__ __forceinline__ void coupling(float x, float* cc, int iter) {
    const int lane = threadIdx.x & 31, warp = threadIdx.x >> 5;
    if (warp < OC) {
        float n1 = warp_sum_f(__ldcg(&g_part[0][lane]));
        float f1 = n1 / (1.f + n1 * n1);
        float S1 = warp_sum_f(x) * (1.f / 32.f);
        float g = f1 * S1;                              // b2 = x * g
        if (iter == 3) {
            float bx = x * g;
            float m = warp_max_f(bx);
            float e = expf(bx - m);
            float Z = warp_sum_f(e);
            float c2 = e / Z;
            float S2 = warp_sum_f(c2 * x);
            float n2 = warp_sum_f(__ldcg(&g_part[1][lane]));
            float f2 = n2 / (1.f + n2 * n2);
            g = g + f2 * S2;                            // b3 = x * g
        }
        float bx = x * g;
        float m = warp_max_f(bx);
        float e = expf(bx - m);
        float Z = warp_sum_f(e);
        cc[lane * OC + warp] = e / Z;
    }
    __syncthreads();
}

// ---------------------------------------------------------------------------
// K_route: all 3 routing iterations + final squash scale, one persistent kernel.
// grid = 32 blocks x 320 threads (exactly NT threads).
// ---------------------------------------------------------------------------
__global__ __launch_bounds__(RTPB) void k_route(float* __restrict__ out) {
    __shared__ float cc[IC * OC];
    __shared__ float redw[RTPB / 32];
    __shared__ float fsh;
    const int tid = threadIdx.x;
    const int lane = tid & 31, warp = tid >> 5;
    const int t = blockIdx.x * RTPB + tid;
    const int o = t >> 10;

    // cache u_dot for this (i=lane, o=warp)
    float x = (warp < OC) ? __ldcg(&g_udot[lane * OC + warp]) : 0.f;

    // ---- iteration 1: uniform coupling 1/32 ----
    float s = 0.f;
#pragma unroll
    for (int i = 0; i < IC; i++) s += g_usum[i * NT + t];
    s *= (1.f / 32.f);
    block_part(s, redw, 0);
    grid_barrier();

    // ---- iteration 2 ----
    coupling(x, cc, 2);
    float s2 = 0.f;
#pragma unroll
    for (int i = 0; i < IC; i++) s2 = fmaf(cc[i * OC + o], g_usum[i * NT + t], s2);
    block_part(s2, redw, 1);
    grid_barrier();

    // ---- iteration 3 ----
    coupling(x, cc, 3);
    float s3 = 0.f;
#pragma unroll
    for (int i = 0; i < IC; i++) s3 = fmaf(cc[i * OC + o], g_usum[i * NT + t], s3);
    block_part(s3, redw, 2);
    grid_barrier();

    // ---- final squash scale ----
    if (tid == 0) {
        float n3 = 0.f;
        for (int k = 0; k < RBLK; k++) n3 += __ldcg(&g_part[2][k]);
        fsh = n3 / (1.f + n3 * n3);
    }
    __syncthreads();
    int b = (t >> 4) & 63, ch = t & 15;
    out[(b * OC + o) * CH + ch] = s3 * fsh;
}

// ---------------------------------------------------------------------------
extern "C" void kernel_launch(void* const* d_in, const int* in_sizes, int n_in,
                              void* d_out, int out_size) {
    const float* u = (const float*)d_in[0];   // [64,32,8,6,6]
    const float* W = (const float*)d_in[1];   // [32,8,6,6,10,16]
    float* out = (float*)d_out;               // [64,10,16]
    (void)in_sizes; (void)n_in; (void)out_size;

    k1_gemm<<<160, 256>>>(u, W);
    k_route<<<RBLK, RTPB>>>(out);
}

// round 3
// speedup vs baseline: 1.9298x; 1.9298x over previous
#include <cuda_runtime.h>
#include <math.h>

// Problem constants
#define IC    32         // in capsules
#define DDIM  288        // ich*w*h
#define OC    10         // out capsules
#define CH    16         // out channels
#define BSZ   64         // batch
#define JDIM  160        // OC*CH
#define NT    10240      // BSZ*OC*CH
#define NSLOT 2560       // NT/4 (float4 slots)
#define RBLK  80         // routing blocks (<=148: co-resident, barrier-safe)
#define RTPB  128        // routing threads per block (4 warps)

// Scratch (device globals: no allocation allowed)
__device__ float g_usum[IC * NT];                 // combined [i][t]
__device__ float g_usum_p[2][IC * NT];            // d-half partials from k1
__device__ float g_udot_p[2][IC * OC];            // d-half partials of u_dot
__device__ __align__(128) float g_part[3][RBLK];  // per-iter L1 partials
__device__ unsigned g_bar_cnt = 0;
__device__ unsigned g_bar_gen = 0;

// ---------------------------------------------------------------------------
// K1: partial GEMM. grid = 32 i * 10 o-chunks(16 j) * 2 d-halves = 640 blocks,
// 128 threads. Each block: 64b x 16j x 144d scalar-FFMA tile (4b x 2j / thread).
// Writes g_usum_p[dh] and g_udot_p[dh][i*OC+o] (block covers exactly one o).
// ---------------------------------------------------------------------------
__global__ __launch_bounds__(128) void k1_gemm(const float* __restrict__ u,
                                               const float* __restrict__ W) {
    const int bid = blockIdx.x;
    const int dh  = bid & 1;
    const int o   = (bid >> 1) % 10;
    const int i   = bid / 20;
    const int j0  = o * 16;
    const int tid = threadIdx.x;
    const int tx  = tid & 7;    // j pair: ch = tx*2 + jj
    const int ty  = tid >> 3;   // b quad: b = ty*4 + bb

    __shared__ float u_t[16][68];   // [dd][b] transposed, pad 68 (16B-aligned float4 rows)
    __shared__ float w_s[16][16];   // [dd][ch]
    __shared__ float redw[4];

    float acc[4][2] = {};

    const float* ug = u + i * DDIM + dh * 144;
    const float* wg = W + (size_t)i * DDIM * JDIM + (size_t)(dh * 144) * JDIM + j0;

    float upf[8], wpf[2];
#pragma unroll
    for (int p = 0; p < 8; p++) { int e = tid + p * 128; upf[p] = ug[(e >> 4) * (IC * DDIM) + (e & 15)]; }
#pragma unroll
    for (int p = 0; p < 2; p++) { int e = tid + p * 128; wpf[p] = wg[(e >> 4) * JDIM + (e & 15)]; }

    for (int c = 0; c < 9; c++) {          // 9 chunks of 16 dd = 144
        __syncthreads();
#pragma unroll
        for (int p = 0; p < 8; p++) { int e = tid + p * 128; u_t[e & 15][e >> 4] = upf[p]; }
#pragma unroll
        for (int p = 0; p < 2; p++) { int e = tid + p * 128; w_s[e >> 4][e & 15] = wpf[p]; }
        __syncthreads();
        if (c < 8) {
            const int d0 = (c + 1) * 16;
#pragma unroll
            for (int p = 0; p < 8; p++) { int e = tid + p * 128; upf[p] = ug[(e >> 4) * (IC * DDIM) + d0 + (e & 15)]; }
#pragma unroll
            for (int p = 0; p < 2; p++) { int e = tid + p * 128; wpf[p] = wg[(d0 + (e >> 4)) * JDIM + (e & 15)]; }
        }
#pragma unroll
        for (int dd = 0; dd < 16; dd++) {
            float4 uv = *(const float4*)&u_t[dd][ty * 4];
            float2 wv = *(const float2*)&w_s[dd][tx * 2];
            acc[0][0] = fmaf(uv.x, wv.x, acc[0][0]); acc[0][1] = fmaf(uv.x, wv.y, acc[0][1]);
            acc[1][0] = fmaf(uv.y, wv.x, acc[1][0]); acc[1][1] = fmaf(uv.y, wv.y, acc[1][1]);
            acc[2][0] = fmaf(uv.z, wv.x, acc[2][0]); acc[2][1] = fmaf(uv.z, wv.y, acc[2][1]);
            acc[3][0] = fmaf(uv.w, wv.x, acc[3][0]); acc[3][1] = fmaf(uv.w, wv.y, acc[3][1]);
        }
    }

    // store partial u_sum; per-thread sum for partial u_dot
    float lsum = 0.f;
    float* dst = g_usum_p[dh] + i * NT + o * 1024;
#pragma unroll
    for (int bb = 0; bb < 4; bb++) {
#pragma unroll
        for (int jj = 0; jj < 2; jj++) {
            int b = ty * 4 + bb, ch = tx * 2 + jj;
            dst[b * CH + ch] = acc[bb][jj];
            lsum += acc[bb][jj];
        }
    }
    // deterministic block reduce: warp butterfly -> 4 partials -> serial add
#pragma unroll
    for (int off = 16; off > 0; off >>= 1) lsum += __shfl_xor_sync(0xffffffffu, lsum, off);
    if ((tid & 31) == 0) redw[tid >> 5] = lsum;
    __syncthreads();
    if (tid == 0) g_udot_p[dh][i * OC + o] = (redw[0] + redw[1]) + (redw[2] + redw[3]);
}

// ---------------------------------------------------------------------------
// warp reductions (butterfly: deterministic)
// ---------------------------------------------------------------------------
__device__ __forceinline__ float warp_sum_f(float v) {
#pragma unroll
    for (int o = 16; o > 0; o >>= 1) v += __shfl_xor_sync(0xffffffffu, v, o);
    return v;
}
__device__ __forceinline__ float warp_max_f(float v) {
#pragma unroll
    for (int o = 16; o > 0; o >>= 1) v = fmaxf(v, __shfl_xor_sync(0xffffffffu, v, o));
    return v;
}

// ---------------------------------------------------------------------------
// software grid barrier (sense-reversal). RBLK=80 blocks all co-resident.
// counter returns to 0 each use -> safe across graph replays.
// ---------------------------------------------------------------------------
__device__ __forceinline__ void grid_barrier() {
    __syncthreads();
    if (threadIdx.x == 0) {
        __threadfence();
        unsigned gen = atomicAdd(&g_bar_gen, 0u);
        unsigned a = atomicAdd(&g_bar_cnt, 1u);
        if (a == RBLK - 1) {
            atomicExch(&g_bar_cnt, 0u);
            __threadfence();
            atomicAdd(&g_bar_gen, 1u);
        } else {
            while (atomicAdd(&g_bar_gen, 0u) == gen) __nanosleep(64);
        }
        __threadfence();
    }
    __syncthreads();
}

// ---------------------------------------------------------------------------
// K_route: iter1 (combine d-halves + n1), iter2, iter3 + squash. One kernel.
// grid = 80 blocks x 128 threads. Warp w handles i-range [8w, 8w+8);
// lane = float4 slot within block. All sweep loads are LDG.128.
// ---------------------------------------------------------------------------
__global__ __launch_bounds__(RTPB) void k_route(float* __restrict__ out) {
    __shared__ float ud[IC * OC];
    __shared__ float cc[IC * OC];
    __shared__ float4 partbuf[4][32];
    const int tid  = threadIdx.x;
    const int lane = tid & 31;
    const int w    = tid >> 5;                 // warp id == i-split
    const int t4   = blockIdx.x * 32 + lane;   // global float4 slot
    const int ot   = t4 >> 8;                  // output capsule of this slot
    const float4* gu0 = (const float4*)g_usum_p[0];
    const float4* gu1 = (const float4*)g_usum_p[1];
    float4* gu = (float4*)g_usum;

    // u_dot = sum of d-half partials
    for (int k = tid; k < IC * OC; k += RTPB)
        ud[k] = __ldcg(&g_udot_p[0][k]) + __ldcg(&g_udot_p[1][k]);
    __syncthreads();

    // ---- iteration 1: combine halves into g_usum; s1 = (1/32) sum_i ----
    float4 s = make_float4(0.f, 0.f, 0.f, 0.f);
#pragma unroll
    for (int r = 0; r < 8; r++) {
        int i = w * 8 + r;
        float4 a = __ldcg(&gu0[i * NSLOT + t4]);
        float4 b = __ldcg(&gu1[i * NSLOT + t4]);
        float4 v = make_float4(a.x + b.x, a.y + b.y, a.z + b.z, a.w + b.w);
        gu[i * NSLOT + t4] = v;
        s.x += v.x; s.y += v.y; s.z += v.z; s.w += v.w;
    }
    partbuf[w][lane] = s;
    __syncthreads();
    if (w == 0) {
        float4 p0 = partbuf[0][lane], p1 = partbuf[1][lane];
        float4 p2 = partbuf[2][lane], p3 = partbuf[3][lane];
        float4 t = make_float4(((p0.x + p1.x) + (p2.x + p3.x)) * (1.f / 32.f),
                               ((p0.y + p1.y) + (p2.y + p3.y)) * (1.f / 32.f),
                               ((p0.z + p1.z) + (p2.z + p3.z)) * (1.f / 32.f),
                               ((p0.w + p1.w) + (p2.w + p3.w)) * (1.f / 32.f));
        float a = (fabsf(t.x) + fabsf(t.y)) + (fabsf(t.z) + fabsf(t.w));
        a = warp_sum_f(a);
        if (lane == 0) g_part[0][blockIdx.x] = a;
    }
    grid_barrier();

    // ---- iteration 2 coupling: c2 ----
    {
        float n1 = 0.f;
        for (int k = lane; k < RBLK; k += 32) n1 += __ldcg(&g_part[0][k]);
        n1 = warp_sum_f(n1);
        float f1 = n1 / (1.f + n1 * n1);
        for (int o = w; o < OC; o += 4) {
            float x = ud[lane * OC + o];
            float S1 = warp_sum_f(x) * (1.f / 32.f);
            float g = f1 * S1;
            float bx = x * g;
            float m = warp_max_f(bx);
            float e = expf(bx - m);
            float Z = warp_sum_f(e);
            cc[lane * OC + o] = e / Z;
        }
    }
    __syncthreads();

    // ---- iteration 2 sweep ----
    float4 s2 = make_float4(0.f, 0.f, 0.f, 0.f);
#pragma unroll
    for (int r = 0; r < 8; r++) {
        int i = w * 8 + r;
        float ci = cc[i * OC + ot];
        float4 v = gu[i * NSLOT + t4];
        s2.x = fmaf(ci, v.x, s2.x); s2.y = fmaf(ci, v.y, s2.y);
        s2.z = fmaf(ci, v.z, s2.z); s2.w = fmaf(ci, v.w, s2.w);
    }
    partbuf[w][lane] = s2;
    __syncthreads();
    if (w == 0) {
        float4 p0 = partbuf[0][lane], p1 = partbuf[1][lane];
        float4 p2 = partbuf[2][lane], p3 = partbuf[3][lane];
        float4 t = make_float4((p0.x + p1.x) + (p2.x + p3.x), (p0.y + p1.y) + (p2.y + p3.y),
                               (p0.z + p1.z) + (p2.z + p3.z), (p0.w + p1.w) + (p2.w + p3.w));
        float a = (fabsf(t.x) + fabsf(t.y)) + (fabsf(t.z) + fabsf(t.w));
        a = warp_sum_f(a);
        if (lane == 0) g_part[1][blockIdx.x] = a;
    }
    grid_barrier();

    // ---- iteration 3 coupling: c3 (rank-1 recurrence through b2) ----
    {
        float n1 = 0.f, n2 = 0.f;
        for (int k = lane; k < RBLK; k += 32) {
            n1 += __ldcg(&g_part[0][k]);
            n2 += __ldcg(&g_part[1][k]);
        }
        n1 = warp_sum_f(n1);
        n2 = warp_sum_f(n2);
        float f1 = n1 / (1.f + n1 * n1);
        float f2 = n2 / (1.f + n2 * n2);
        for (int o = w; o < OC; o += 4) {
            float x = ud[lane * OC + o];
            float S1 = warp_sum_f(x) * (1.f / 32.f);
            float g = f1 * S1;                       // b2 = x*g
            float bx = x * g;
            float m = warp_max_f(bx);
            float e = expf(bx - m);
            float Z = warp_sum_f(e);
            float c2 = e / Z;
            float S2 = warp_sum_f(c2 * x);
            g = g + f2 * S2;                         // b3 = x*g
            bx = x * g;
            m = warp_max_f(bx);
            e = expf(bx - m);
            Z = warp_sum_f(e);
            cc[lane * OC + o] = e / Z;
        }
    }
    __syncthreads();

    // ---- iteration 3 sweep ----
    float4 s3 = make_float4(0.f, 0.f, 0.f, 0.f);
#pragma unroll
    for (int r = 0; r < 8; r++) {
        int i = w * 8 + r;
        float ci = cc[i * OC + ot];
        float4 v = gu[i * NSLOT + t4];
        s3.x = fmaf(ci, v.x, s3.x); s3.y = fmaf(ci, v.y, s3.y);
        s3.z = fmaf(ci, v.z, s3.z); s3.w = fmaf(ci, v.w, s3.w);
    }
    partbuf[w][lane] = s3;
    __syncthreads();
    float4 t3 = make_float4(0.f, 0.f, 0.f, 0.f);
    if (w == 0) {
        float4 p0 = partbuf[0][lane], p1 = partbuf[1][lane];
        float4 p2 = partbuf[2][lane], p3 = partbuf[3][lane];
        t3 = make_float4((p0.x + p1.x) + (p2.x + p3.x), (p0.y + p1.y) + (p2.y + p3.y),
                         (p0.z + p1.z) + (p2.z + p3.z), (p0.w + p1.w) + (p2.w + p3.w));
        float a = (fabsf(t3.x) + fabsf(t3.y)) + (fabsf(t3.z) + fabsf(t3.w));
        a = warp_sum_f(a);
        if (lane == 0) g_part[2][blockIdx.x] = a;
    }
    grid_barrier();

    // ---- final squash scale + output (warp 0 only; deterministic n3) ----
    if (w == 0) {
        float n3 = 0.f;
        for (int k = lane; k < RBLK; k += 32) n3 += __ldcg(&g_part[2][k]);
        n3 = warp_sum_f(n3);
        float fsh = n3 / (1.f + n3 * n3);
        // element base for this slot
        int e0 = t4 * 4;
        int b = (e0 >> 4) & 63;
        int ch0 = e0 & 15;
        float4 res = make_float4(t3.x * fsh, t3.y * fsh, t3.z * fsh, t3.w * fsh);
        ((float4*)out)[(b * OC + ot) * 4 + (ch0 >> 2)] = res;
    }
}

// ---------------------------------------------------------------------------
extern "C" void kernel_launch(void* const* d_in, const int* in_sizes, int n_in,
                              void* d_out, int out_size) {
    const float* u = (const float*)d_in[0];   // [64,32,8,6,6]
    const float* W = (const float*)d_in[1];   // [32,8,6,6,10,16]
    float* out = (float*)d_out;               // [64,10,16]
    (void)in_sizes; (void)n_in; (void)out_size;

    k1_gemm<<<640, 128>>>(u, W);
    k_route<<<RBLK, RTPB>>>(out);
}